// round 5
// baseline (speedup 1.0000x reference)
#include <cuda_runtime.h>
#include <cuda_bf16.h>
#include <math.h>
#include <stdint.h>

#define NS 25
#define NQ 50
#define NV 75
#define SEQ 12
#define DIM 1152
#define HH 2
#define DH 576
#define NTUP 220
#define WAY 5
#define SHOT 5
#define KROWS (NQ*NTUP)      /* 11000 */
#define MPAD  11008
#define SKCOL (SHOT*NTUP)    /* 1100 */
#define SKP   1152
#define DHP   640
#define KPAD  1152

// ---------------- device scratch ----------------
__device__ float g_pe[SEQ*DIM];
__device__ int   g_tuples[NTUP*3];
__device__ __align__(16) __nv_bfloat16 g_Ap[1024*DIM];
__device__ __align__(16) __nv_bfloat16 g_wT[6912*DIM];
__device__ float g_P[1024*6912];
__device__ __align__(16) __nv_bfloat16 g_qk[HH][(size_t)MPAD*DH];
__device__ __align__(16) __nv_bfloat16 g_skz[WAY*HH][(size_t)SKP*DH];
__device__ __align__(16) __nv_bfloat16 g_svT[WAY*HH][(size_t)DHP*KPAD];
__device__ float g_qv[(size_t)KROWS*DIM];
__device__ __align__(16) __nv_bfloat16 g_scores[WAY*HH][(size_t)MPAD*SKP];  // bf16 now
__device__ __align__(16) __nv_bfloat16 g_attn[WAY*HH][(size_t)MPAD*KPAD];

// ---------------- helpers ----------------
__device__ __forceinline__ uint32_t smem_u32(const void* p){
    uint32_t a;
    asm("{ .reg .u64 t; cvta.to.shared.u64 t, %1; cvt.u32.u64 %0, t; }" : "=r"(a) : "l"(p));
    return a;
}
#define SW128(x) ((x) ^ (((x)>>3)&0x70))

__device__ __forceinline__ void ldm4(uint32_t* r, uint32_t addr){
    asm volatile("ldmatrix.sync.aligned.m8n8.x4.shared.b16 {%0,%1,%2,%3}, [%4];"
        : "=r"(r[0]), "=r"(r[1]), "=r"(r[2]), "=r"(r[3]) : "r"(addr));
}
__device__ __forceinline__ void mma16816(float* c, const uint32_t* a, uint32_t b0, uint32_t b1){
    asm volatile("mma.sync.aligned.m16n8k16.row.col.f32.bf16.bf16.f32 "
        "{%0,%1,%2,%3}, {%4,%5,%6,%7}, {%8,%9}, {%0,%1,%2,%3};"
        : "+f"(c[0]), "+f"(c[1]), "+f"(c[2]), "+f"(c[3])
        : "r"(a[0]), "r"(a[1]), "r"(a[2]), "r"(a[3]), "r"(b0), "r"(b1));
}
__device__ __forceinline__ void cpa16(uint32_t dst, const void* src){
    asm volatile("cp.async.cg.shared.global [%0], [%1], 16;" :: "r"(dst), "l"(src));
}

// ---------------- init ----------------
__global__ void k_init(float* out) {
    int tid = threadIdx.x;
    for (int i = tid; i < SEQ*576; i += blockDim.x) {
        int p = i / 576, j = i % 576;
        double dv = exp(-(double)(2*j) * (log(10000.0) / 1152.0));
        double ang = (double)p * dv;
        g_pe[p*DIM + 2*j]     = (float)(sin(ang) * 0.1);
        g_pe[p*DIM + 2*j + 1] = (float)(cos(ang) * 0.1);
    }
    if (tid < NQ*WAY) out[tid] = 0.f;
    if (tid == 0) {
        int idx = 0;
        for (int a = 0; a < SEQ; a++)
            for (int b = a+1; b < SEQ; b++)
                for (int c = b+1; c < SEQ; c++) {
                    g_tuples[idx*3+0]=a; g_tuples[idx*3+1]=b; g_tuples[idx*3+2]=c; idx++;
                }
    }
}

__global__ void k_zero(){
    size_t i = (size_t)blockIdx.x*256 + threadIdx.x;
    size_t total = (size_t)WAY*HH*DHP*KPAD/8;
    if (i < total) ((uint4*)g_svT)[i] = make_uint4(0,0,0,0);
}

__global__ __launch_bounds__(128) void k_prepA(const float* __restrict__ sup,
                                               const float* __restrict__ qry){
    int m = blockIdx.x; int v = m/SEQ, f = m%SEQ;
    const float* src = (v < NS) ? sup + (size_t)m*DIM
                                : qry + ((size_t)(v-NS)*SEQ + f)*DIM;
    for (int i = threadIdx.x; i < DIM; i += 128)
        g_Ap[(size_t)m*DIM + i] = __float2bfloat16(src[i] + g_pe[f*DIM + i]);
}

__global__ void k_transW(const float* __restrict__ kw, const float* __restrict__ vw){
    __shared__ float t[32][33];
    int z = blockIdx.z; int j = z>>1, which = z&1;
    const float* W = which ? vw : kw;
    int o0 = blockIdx.x*32, k0 = blockIdx.y*32;
    int tx = threadIdx.x, ty = threadIdx.y;
    t[ty][tx] = W[(size_t)(j*1152 + k0 + ty)*1152 + o0 + tx];
    __syncthreads();
    g_wT[(size_t)(j*2304 + which*1152 + o0 + ty)*1152 + k0 + tx] = __float2bfloat16(t[tx][ty]);
}

// ---------------- bf16 NT GEMM, 64x64 warp tiles, 3-stage cp.async ----------------
// C[M,N] = A[M,K] @ B[N,K]^T. 128x128 CTA tile, 4 warps (2x2), K = KT*64.
// OT=0: fp32 store. OT=1: bf16 store. OT=2: fused -(qv-C)^2 logits.
template<int OT>
__global__ __launch_bounds__(128, 2) void k_gemm2(
    const __nv_bfloat16* __restrict__ A, int lda, int amod, size_t sA,
    const __nv_bfloat16* __restrict__ B, int ldb, size_t sB,
    void* __restrict__ Cv, int ldc, size_t sC, int KT,
    const float* __restrict__ qv, float* __restrict__ out)
{
    extern __shared__ char smem[];
    const int tid = threadIdx.x, wid = tid>>5, lane = tid&31;
    const int wm = wid & 1, wn = wid >> 1;
    const int z = blockIdx.z;
    A += (size_t)(amod ? (z % amod) : z) * sA;
    B += (size_t)z * sB;
    const int m0 = blockIdx.y*128, n0 = blockIdx.x*128;
    const uint32_t sbase = smem_u32(smem);

    const int lrow = tid >> 3, lch = tid & 7;   // 16 rows per pass, 8 passes
    float acc[4][8][4];
    #pragma unroll
    for (int i=0;i<4;i++) for (int j=0;j<8;j++) for (int r=0;r<4;r++) acc[i][j][r]=0.f;

    auto load_tile = [&](int kt, int buf){
        const __nv_bfloat16* Ab = A + (size_t)m0*lda + kt*64;
        const __nv_bfloat16* Bb = B + (size_t)n0*ldb + kt*64;
        uint32_t da = sbase + buf*32768;
        uint32_t db = da + 16384;
        #pragma unroll
        for (int c = 0; c < 8; c++){
            int row = lrow + c*16;
            uint32_t so = SW128(row*128 + lch*16);
            cpa16(da + so, Ab + (size_t)row*lda + lch*8);
            cpa16(db + so, Bb + (size_t)row*ldb + lch*8);
        }
        asm volatile("cp.async.commit_group;");
    };

    load_tile(0, 0);
    load_tile(1, 1);

    for (int kt = 0; kt < KT; kt++){
        if (kt + 1 < KT) asm volatile("cp.async.wait_group 1;");
        else             asm volatile("cp.async.wait_group 0;");
        __syncthreads();
        if (kt + 2 < KT) load_tile(kt + 2, (kt + 2) % 3);
        const int buf = kt % 3;
        const uint32_t sA_ = sbase + buf*32768;
        const uint32_t sB_ = sA_ + 16384;
        #pragma unroll
        for (int kk = 0; kk < 4; kk++){
            const int colb = kk*32 + ((lane >> 4) << 4);
            uint32_t a[4][4], b[4][4];
            #pragma unroll
            for (int i = 0; i < 4; i++){
                int row = wm*64 + i*16 + (lane & 15);
                ldm4(a[i], sA_ + SW128(row*128 + colb));
            }
            #pragma unroll
            for (int j = 0; j < 4; j++){
                int row = wn*64 + j*16 + (lane & 15);
                ldm4(b[j], sB_ + SW128(row*128 + colb));
            }
            #pragma unroll
            for (int i = 0; i < 4; i++)
                #pragma unroll
                for (int jj = 0; jj < 8; jj++)
                    mma16816(acc[i][jj], a[i], b[jj>>1][jj&1], b[jj>>1][2+(jj&1)]);
        }
        __syncthreads();
    }

    if (OT == 0) {
        float* C = (float*)Cv + (size_t)z * sC;
        #pragma unroll
        for (int i = 0; i < 4; i++){
            int r0 = m0 + wm*64 + i*16 + (lane >> 2);
            #pragma unroll
            for (int jj = 0; jj < 8; jj++){
                int cc = n0 + wn*64 + jj*8 + (lane & 3)*2;
                *(float2*)(C + (size_t)r0*ldc + cc)     = make_float2(acc[i][jj][0], acc[i][jj][1]);
                *(float2*)(C + (size_t)(r0+8)*ldc + cc) = make_float2(acc[i][jj][2], acc[i][jj][3]);
            }
        }
    } else if (OT == 1) {
        __nv_bfloat16* C = (__nv_bfloat16*)Cv + (size_t)z * sC;
        #pragma unroll
        for (int i = 0; i < 4; i++){
            int r0 = m0 + wm*64 + i*16 + (lane >> 2);
            #pragma unroll
            for (int jj = 0; jj < 8; jj++){
                int cc = n0 + wn*64 + jj*8 + (lane & 3)*2;
                *(__nv_bfloat162*)(C + (size_t)r0*ldc + cc)
                    = __floats2bfloat162_rn(acc[i][jj][0], acc[i][jj][1]);
                *(__nv_bfloat162*)(C + (size_t)(r0+8)*ldc + cc)
                    = __floats2bfloat162_rn(acc[i][jj][2], acc[i][jj][3]);
            }
        }
    } else {
        const int w = z >> 1, h = z & 1;
        const int q0 = m0 / NTUP;
        const int qb = (q0 + 1) * NTUP;
        float s[2] = {0.f, 0.f};
        #pragma unroll
        for (int i = 0; i < 4; i++){
            int rb = m0 + wm*64 + i*16 + (lane >> 2);
            #pragma unroll
            for (int rr = 0; rr < 2; rr++){
                int row = rb + rr*8;
                if (row < KROWS) {
                    const float* qrow = qv + (size_t)row*DIM + h*DH;
                    int qi = (row >= qb) ? 1 : 0;
                    float part = 0.f;
                    #pragma unroll
                    for (int jj = 0; jj < 8; jj++){
                        int cc = n0 + wn*64 + jj*8 + (lane & 3)*2;
                        if (cc < DH) {
                            float d0 = qrow[cc]   - acc[i][jj][rr*2+0];
                            float d1 = qrow[cc+1] - acc[i][jj][rr*2+1];
                            part += d0*d0 + d1*d1;
                        }
                    }
                    s[qi] += part;
                }
            }
        }
        float* red = (float*)smem;
        red[tid] = s[0]; red[128 + tid] = s[1];
        __syncthreads();
        #pragma unroll
        for (int st = 64; st > 0; st >>= 1){
            if (tid < st) { red[tid] += red[tid+st]; red[128+tid] += red[128+tid+st]; }
            __syncthreads();
        }
        if (tid == 0 && red[0] != 0.f) atomicAdd(&out[q0*WAY + w], -red[0] * (1.f/NTUP));
        if (tid == 1 && q0 + 1 < NQ && red[128] != 0.f)
            atomicAdd(&out[(q0+1)*WAY + w], -red[128] * (1.f/NTUP));
    }
}

// ---------------- tuple combine + bias + LayerNorm ----------------
__global__ __launch_bounds__(128) void k_combine(
    const float* __restrict__ kb, const float* __restrict__ vb,
    const float* __restrict__ lg, const float* __restrict__ lb)
{
    const int bid = blockIdx.x;
    const int v = bid / NTUP, t = bid % NTUP;
    const int tid = threadIdx.x;
    __shared__ float red[128];
    __shared__ int fr[3];
    if (tid < 3) fr[tid] = g_tuples[t*3 + tid];
    __syncthreads();

    float kv[9], vv[9];
    float lsum = 0.f, lsq = 0.f;
    #pragma unroll
    for (int ii = 0; ii < 9; ii++) {
        int d = tid + ii*128;
        float ka = kb[d], va = vb[d];
        #pragma unroll
        for (int j = 0; j < 3; j++) {
            const float* p = g_P + (size_t)(v*SEQ + fr[j])*6912 + j*2304;
            ka += p[d]; va += p[1152 + d];
        }
        kv[ii] = ka; vv[ii] = va;
        lsum += ka; lsq += ka*ka;
    }
    red[tid] = lsum; __syncthreads();
    for (int s = 64; s > 0; s >>= 1) { if (tid < s) red[tid] += red[tid+s]; __syncthreads(); }
    float mu = red[0] * (1.f/1152.f);
    __syncthreads();
    red[tid] = lsq; __syncthreads();
    for (int s = 64; s > 0; s >>= 1) { if (tid < s) red[tid] += red[tid+s]; __syncthreads(); }
    float var = red[0] * (1.f/1152.f) - mu*mu;
    float rstd = rsqrtf(var + 1e-5f);

    int w = 0, s = 0;
    if (v < NS) { w = v / SHOT; s = v % SHOT; }
    #pragma unroll
    for (int ii = 0; ii < 9; ii++) {
        int d = tid + ii*128;
        int h = d / DH, dd = d % DH;
        float o = (kv[ii] - mu) * rstd * lg[d] + lb[d];
        if (v < NS) {
            int zz = w*2 + h;
            g_skz[zz][(size_t)(s*NTUP + t)*DH + dd] = __float2bfloat16(o);
            g_svT[zz][(size_t)dd*KPAD + s*NTUP + t] = __float2bfloat16(vv[ii]);
        } else {
            g_qk[h][(size_t)((v-NS)*NTUP + t)*DH + dd] = __float2bfloat16(o);
            g_qv[(size_t)((v-NS)*NTUP + t)*DIM + d] = vv[ii];
        }
    }
}

// ---------------- softmax: bf16 scores -> bf16 attn (pairs) ----------------
__global__ __launch_bounds__(128) void k_softmax() {
    const int z = blockIdx.x / KROWS;
    const int r = blockIdx.x % KROWS;
    const __nv_bfloat162* src = (const __nv_bfloat162*)(g_scores[z] + (size_t)r * SKP);
    __nv_bfloat162* dst = (__nv_bfloat162*)(g_attn[z] + (size_t)r * KPAD);
    const int tid = threadIdx.x;
    __shared__ float red[128];
    float e0[5], e1[5];
    float lmax = -1e30f;
    #pragma unroll
    for (int ii = 0; ii < 5; ii++) {
        int i = tid + ii*128;
        if (i < 550) {
            float2 v = __bfloat1622float2(src[i]);
            e0[ii] = v.x * (1.f/24.f); e1[ii] = v.y * (1.f/24.f);
            lmax = fmaxf(lmax, fmaxf(e0[ii], e1[ii]));
        } else { e0[ii] = -1e30f; e1[ii] = -1e30f; }
    }
    red[tid] = lmax; __syncthreads();
    for (int s = 64; s > 0; s >>= 1) { if (tid < s) red[tid] = fmaxf(red[tid], red[tid+s]); __syncthreads(); }
    float mx = red[0];
    __syncthreads();
    float lsum = 0.f;
    #pragma unroll
    for (int ii = 0; ii < 5; ii++) {
        int i = tid + ii*128;
        if (i < 550) {
            e0[ii] = expf(e0[ii] - mx); e1[ii] = expf(e1[ii] - mx);
            lsum += e0[ii] + e1[ii];
        } else { e0[ii] = 0.f; e1[ii] = 0.f; }
    }
    red[tid] = lsum; __syncthreads();
    for (int s = 64; s > 0; s >>= 1) { if (tid < s) red[tid] += red[tid+s]; __syncthreads(); }
    float inv = 1.f / red[0];
    #pragma unroll
    for (int ii = 0; ii < 5; ii++) {
        int i = tid + ii*128;
        if (i < 576) dst[i] = __floats2bfloat162_rn(e0[ii]*inv, e1[ii]*inv);
    }
}

// ---------------- launch ----------------
extern "C" void kernel_launch(void* const* d_in, const int* in_sizes, int n_in,
                              void* d_out, int out_size)
{
    const float* support = (const float*)d_in[0];
    const float* queries = (const float*)d_in[1];
    const float* k_w  = (const float*)d_in[3];
    const float* k_b  = (const float*)d_in[4];
    const float* v_w  = (const float*)d_in[5];
    const float* v_b  = (const float*)d_in[6];
    const float* ln_g = (const float*)d_in[7];
    const float* ln_b = (const float*)d_in[8];
    float* out = (float*)d_out;

    void *pAp, *pWT, *pP, *pQK, *pSKZ, *pSVT, *pSC, *pATT, *pQV;
    cudaGetSymbolAddress(&pAp,  g_Ap);
    cudaGetSymbolAddress(&pWT,  g_wT);
    cudaGetSymbolAddress(&pP,   g_P);
    cudaGetSymbolAddress(&pQK,  g_qk);
    cudaGetSymbolAddress(&pSKZ, g_skz);
    cudaGetSymbolAddress(&pSVT, g_svT);
    cudaGetSymbolAddress(&pSC,  g_scores);
    cudaGetSymbolAddress(&pATT, g_attn);
    cudaGetSymbolAddress(&pQV,  g_qv);

    const int SMEM_BYTES = 3*32768;
    cudaFuncSetAttribute(k_gemm2<0>, cudaFuncAttributeMaxDynamicSharedMemorySize, SMEM_BYTES);
    cudaFuncSetAttribute(k_gemm2<1>, cudaFuncAttributeMaxDynamicSharedMemorySize, SMEM_BYTES);
    cudaFuncSetAttribute(k_gemm2<2>, cudaFuncAttributeMaxDynamicSharedMemorySize, SMEM_BYTES);

    k_init<<<1, 256>>>(out);
    {
        size_t tot = (size_t)WAY*HH*DHP*KPAD/8;
        k_zero<<<(int)((tot + 255)/256), 256>>>();
    }
    k_prepA<<<NV*SEQ, 128>>>(support, queries);
    k_transW<<<dim3(36, 36, 6), dim3(32, 32)>>>(k_w, v_w);

    // proj: C[1024(900), 6912] = Ap @ wT^T, K=1152, fp32 out
    k_gemm2<0><<<dim3(54, 8, 1), 128, SMEM_BYTES>>>(
        (const __nv_bfloat16*)pAp, DIM, 1, 0,
        (const __nv_bfloat16*)pWT, DIM, 0,
        pP, 6912, 0, 18, nullptr, nullptr);

    k_combine<<<NV*NTUP, 128>>>(k_b, v_b, ln_g, ln_b);

    // scores: per z: C[11008, 1152] = qk[z%2] @ skz[z]^T, K=576, bf16 out
    k_gemm2<1><<<dim3(SKP/128, MPAD/128, WAY*HH), 128, SMEM_BYTES>>>(
        (const __nv_bfloat16*)pQK, DH, 2, (size_t)MPAD*DH,
        (const __nv_bfloat16*)pSKZ, DH, (size_t)SKP*DH,
        pSC, SKP, (size_t)MPAD*SKP, 9, nullptr, nullptr);

    k_softmax<<<WAY*HH*KROWS, 128>>>();

    // proto + fused logits
    k_gemm2<2><<<dim3(DHP/128, MPAD/128, WAY*HH), 128, SMEM_BYTES>>>(
        (const __nv_bfloat16*)pATT, KPAD, 0, (size_t)MPAD*KPAD,
        (const __nv_bfloat16*)pSVT, KPAD, (size_t)DHP*KPAD,
        nullptr, 0, 0, 18, (const float*)pQV, out);
}

// round 6
// speedup vs baseline: 1.1592x; 1.1592x over previous
#include <cuda_runtime.h>
#include <cuda_fp16.h>
#include <math.h>
#include <stdint.h>

#define NS 25
#define NQ 50
#define NV 75
#define SEQ 12
#define DIM 1152
#define HH 2
#define DH 576
#define NTUP 220
#define WAY 5
#define SHOT 5
#define KROWS (NQ*NTUP)      /* 11000 */
#define MPAD  11008
#define SKCOL (SHOT*NTUP)    /* 1100 */
#define SKP   1152
#define KPAD  1152
#define RS24  0.20412414523193154f   /* 1/sqrt(24) */

// ---------------- device scratch ----------------
__device__ float g_pe[SEQ*DIM];
__device__ int   g_tuples[NTUP*3];
__device__ __align__(16) __half g_Ap[1024*DIM];
__device__ __align__(16) __half g_wT[6912*DIM];
__device__ float g_P[1024*6912];
__device__ __align__(16) __half g_qk[HH][(size_t)MPAD*DH];
__device__ __align__(16) __half g_skz[WAY*HH][(size_t)SKP*DH];
__device__ __align__(16) __half g_svT[WAY*HH][(size_t)DH*KPAD];
__device__ float g_qv[(size_t)KROWS*DIM];
__device__ __align__(16) __half g_scores[WAY*HH][(size_t)MPAD*SKP];
__device__ __align__(16) __half g_attn[WAY*HH][(size_t)MPAD*KPAD];

// ---------------- helpers ----------------
__device__ __forceinline__ uint32_t smem_u32(const void* p){
    uint32_t a;
    asm("{ .reg .u64 t; cvta.to.shared.u64 t, %1; cvt.u32.u64 %0, t; }" : "=r"(a) : "l"(p));
    return a;
}
#define SW128(x) ((x) ^ (((x)>>3)&0x70))

__device__ __forceinline__ void ldm4(uint32_t* r, uint32_t addr){
    asm volatile("ldmatrix.sync.aligned.m8n8.x4.shared.b16 {%0,%1,%2,%3}, [%4];"
        : "=r"(r[0]), "=r"(r[1]), "=r"(r[2]), "=r"(r[3]) : "r"(addr));
}
// f16 accumulate (the 2x-rate hypothesis under test)
__device__ __forceinline__ void mma16816h(uint32_t* c, const uint32_t* a, uint32_t b0, uint32_t b1){
    asm volatile("mma.sync.aligned.m16n8k16.row.col.f16.f16.f16.f16 "
        "{%0,%1}, {%2,%3,%4,%5}, {%6,%7}, {%0,%1};"
        : "+r"(c[0]), "+r"(c[1])
        : "r"(a[0]), "r"(a[1]), "r"(a[2]), "r"(a[3]), "r"(b0), "r"(b1));
}
__device__ __forceinline__ void cpa16(uint32_t dst, const void* src){
    asm volatile("cp.async.cg.shared.global [%0], [%1], 16;" :: "r"(dst), "l"(src));
}

// ---------------- init ----------------
__global__ void k_init(float* out) {
    int tid = threadIdx.x;
    for (int i = tid; i < SEQ*576; i += blockDim.x) {
        int p = i / 576, j = i % 576;
        double dv = exp(-(double)(2*j) * (log(10000.0) / 1152.0));
        double ang = (double)p * dv;
        g_pe[p*DIM + 2*j]     = (float)(sin(ang) * 0.1);
        g_pe[p*DIM + 2*j + 1] = (float)(cos(ang) * 0.1);
    }
    if (tid < NQ*WAY) out[tid] = 0.f;
    if (tid == 0) {
        int idx = 0;
        for (int a = 0; a < SEQ; a++)
            for (int b = a+1; b < SEQ; b++)
                for (int c = b+1; c < SEQ; c++) {
                    g_tuples[idx*3+0]=a; g_tuples[idx*3+1]=b; g_tuples[idx*3+2]=c; idx++;
                }
    }
}

__global__ void k_zero16(uint4* p, size_t n){
    size_t i = (size_t)blockIdx.x*256 + threadIdx.x;
    if (i < n) p[i] = make_uint4(0,0,0,0);
}

__global__ __launch_bounds__(128) void k_prepA(const float* __restrict__ sup,
                                               const float* __restrict__ qry){
    int m = blockIdx.x; int v = m/SEQ, f = m%SEQ;
    const float* src = (v < NS) ? sup + (size_t)m*DIM
                                : qry + ((size_t)(v-NS)*SEQ + f)*DIM;
    for (int i = threadIdx.x; i < DIM; i += 128)
        g_Ap[(size_t)m*DIM + i] = __float2half(src[i] + g_pe[f*DIM + i]);
}

__global__ void k_transW(const float* __restrict__ kw, const float* __restrict__ vw){
    __shared__ float t[32][33];
    int z = blockIdx.z; int j = z>>1, which = z&1;
    const float* W = which ? vw : kw;
    int o0 = blockIdx.x*32, k0 = blockIdx.y*32;
    int tx = threadIdx.x, ty = threadIdx.y;
    t[ty][tx] = W[(size_t)(j*1152 + k0 + ty)*1152 + o0 + tx];
    __syncthreads();
    g_wT[(size_t)(j*2304 + which*1152 + o0 + ty)*1152 + k0 + tx] = __float2half(t[tx][ty]);
}

// ---------------- f16 NT GEMM, f16 accumulate ----------------
// C[M,N] = A[M,K] @ B[N,K]^T. CTA tile 128 x (GN*WN). 8 warps (GM x GN). K = KT*64.
// OT=0: fp32 store. OT=1: f16 store. OT=2: fused -(qv-C)^2 logits.
template<int OT, int WM, int WN, int GM, int GN, int STAGES>
__global__ __launch_bounds__(256, 2) void k_gemmh(
    const __half* __restrict__ A, int lda, int amod, size_t sA,
    const __half* __restrict__ B, int ldb, size_t sB,
    void* __restrict__ Cv, int ldc, size_t sC, int KT,
    const float* __restrict__ qv, float* __restrict__ out)
{
    constexpr int BN  = GN*WN;
    constexpr int ASZ = 128*128;        // A stage bytes
    constexpr int BSZ = BN*128;         // B stage bytes
    constexpr int STG = ASZ + BSZ;
    extern __shared__ char smem[];
    const int tid = threadIdx.x, wid = tid>>5, lane = tid&31;
    const int wm = wid % GM, wn = wid / GM;
    const int z = blockIdx.z;
    A += (size_t)(amod ? (z % amod) : z) * sA;
    B += (size_t)z * sB;
    const int m0 = blockIdx.y*128, n0 = blockIdx.x*BN;
    const uint32_t sbase = smem_u32(smem);
    const int lrow = tid >> 3, lch = tid & 7;

    uint32_t acc[WM/16][WN/8][2];
    #pragma unroll
    for (int i=0;i<WM/16;i++) for (int j=0;j<WN/8;j++){ acc[i][j][0]=0u; acc[i][j][1]=0u; }

    auto load_tile = [&](int kt, int buf){
        const __half* Ab = A + (size_t)m0*lda + kt*64;
        const __half* Bb = B + (size_t)n0*ldb + kt*64;
        uint32_t da = sbase + buf*STG;
        uint32_t db = da + ASZ;
        #pragma unroll
        for (int c = 0; c < 4; c++){
            int row = lrow + c*32;
            cpa16(da + SW128(row*128 + lch*16), Ab + (size_t)row*lda + lch*8);
        }
        #pragma unroll
        for (int c = 0; c < BN/32; c++){
            int row = lrow + c*32;
            cpa16(db + SW128(row*128 + lch*16), Bb + (size_t)row*ldb + lch*8);
        }
        asm volatile("cp.async.commit_group;");
    };

    #pragma unroll
    for (int s = 0; s < STAGES-1; s++) load_tile(s, s);

    for (int kt = 0; kt < KT; kt++){
        if (STAGES == 3 && kt + 1 < KT) asm volatile("cp.async.wait_group 1;");
        else                            asm volatile("cp.async.wait_group 0;");
        __syncthreads();
        if (kt + STAGES-1 < KT) load_tile(kt + STAGES-1, (kt + STAGES-1) % STAGES);
        const uint32_t sA_ = sbase + (kt % STAGES)*STG;
        const uint32_t sB_ = sA_ + ASZ;
        #pragma unroll
        for (int kk = 0; kk < 4; kk++){
            const int colb = kk*32 + ((lane >> 4) << 4);
            uint32_t a[WM/16][4], b[WN/16][4];
            #pragma unroll
            for (int i = 0; i < WM/16; i++)
                ldm4(a[i], sA_ + SW128((wm*WM + i*16 + (lane & 15))*128 + colb));
            #pragma unroll
            for (int j = 0; j < WN/16; j++)
                ldm4(b[j], sB_ + SW128((wn*WN + j*16 + (lane & 15))*128 + colb));
            #pragma unroll
            for (int i = 0; i < WM/16; i++)
                #pragma unroll
                for (int jj = 0; jj < WN/8; jj++)
                    mma16816h(acc[i][jj], a[i], b[jj>>1][jj&1], b[jj>>1][2+(jj&1)]);
        }
        __syncthreads();
    }

    if (OT == 0) {
        float* C = (float*)Cv + (size_t)z * sC;
        #pragma unroll
        for (int i = 0; i < WM/16; i++){
            int r0 = m0 + wm*WM + i*16 + (lane >> 2);
            #pragma unroll
            for (int jj = 0; jj < WN/8; jj++){
                int cc = n0 + wn*WN + jj*8 + (lane & 3)*2;
                float2 v0 = __half22float2(*(__half2*)&acc[i][jj][0]);
                float2 v1 = __half22float2(*(__half2*)&acc[i][jj][1]);
                *(float2*)(C + (size_t)r0*ldc + cc)     = v0;
                *(float2*)(C + (size_t)(r0+8)*ldc + cc) = v1;
            }
        }
    } else if (OT == 1) {
        __half* C = (__half*)Cv + (size_t)z * sC;
        #pragma unroll
        for (int i = 0; i < WM/16; i++){
            int r0 = m0 + wm*WM + i*16 + (lane >> 2);
            #pragma unroll
            for (int jj = 0; jj < WN/8; jj++){
                int cc = n0 + wn*WN + jj*8 + (lane & 3)*2;
                *(uint32_t*)(C + (size_t)r0*ldc + cc)     = acc[i][jj][0];
                *(uint32_t*)(C + (size_t)(r0+8)*ldc + cc) = acc[i][jj][1];
            }
        }
    } else {
        const int w = z >> 1, h = z & 1;
        const int q0 = m0 / NTUP;
        const int qb = (q0 + 1) * NTUP;
        float s0 = 0.f, s1 = 0.f;
        #pragma unroll
        for (int i = 0; i < WM/16; i++){
            int rb = m0 + wm*WM + i*16 + (lane >> 2);
            #pragma unroll
            for (int rr = 0; rr < 2; rr++){
                int row = rb + rr*8;
                if (row < KROWS) {
                    const float* qrow = qv + (size_t)row*DIM + h*DH;
                    float part = 0.f;
                    #pragma unroll
                    for (int jj = 0; jj < WN/8; jj++){
                        int cc = n0 + wn*WN + jj*8 + (lane & 3)*2;   // < 576 by construction
                        float2 v = __half22float2(*(__half2*)&acc[i][jj][rr]);
                        float d0 = qrow[cc]   - v.x;
                        float d1 = qrow[cc+1] - v.y;
                        part += d0*d0 + d1*d1;
                    }
                    if (row >= qb) s1 += part; else s0 += part;
                }
            }
        }
        float* red = (float*)smem;
        red[tid] = s0; red[256 + tid] = s1;
        __syncthreads();
        #pragma unroll
        for (int st = 128; st > 0; st >>= 1){
            if (tid < st) { red[tid] += red[tid+st]; red[256+tid] += red[256+tid+st]; }
            __syncthreads();
        }
        if (tid == 0 && red[0]   != 0.f) atomicAdd(&out[q0*WAY + w], -red[0]   * (1.f/NTUP));
        if (tid == 1 && q0 + 1 < NQ && red[256] != 0.f)
            atomicAdd(&out[(q0+1)*WAY + w], -red[256] * (1.f/NTUP));
    }
}

// ---------------- tuple combine + bias + LayerNorm ----------------
__global__ __launch_bounds__(128) void k_combine(
    const float* __restrict__ kb, const float* __restrict__ vb,
    const float* __restrict__ lg, const float* __restrict__ lb)
{
    const int bid = blockIdx.x;
    const int v = bid / NTUP, t = bid % NTUP;
    const int tid = threadIdx.x;
    __shared__ float red[128];
    __shared__ int fr[3];
    if (tid < 3) fr[tid] = g_tuples[t*3 + tid];
    __syncthreads();

    float kv[9], vv[9];
    float lsum = 0.f, lsq = 0.f;
    #pragma unroll
    for (int ii = 0; ii < 9; ii++) {
        int d = tid + ii*128;
        float ka = kb[d], va = vb[d];
        #pragma unroll
        for (int j = 0; j < 3; j++) {
            const float* p = g_P + (size_t)(v*SEQ + fr[j])*6912 + j*2304;
            ka += p[d]; va += p[1152 + d];
        }
        kv[ii] = ka; vv[ii] = va;
        lsum += ka; lsq += ka*ka;
    }
    red[tid] = lsum; __syncthreads();
    for (int s = 64; s > 0; s >>= 1) { if (tid < s) red[tid] += red[tid+s]; __syncthreads(); }
    float mu = red[0] * (1.f/1152.f);
    __syncthreads();
    red[tid] = lsq; __syncthreads();
    for (int s = 64; s > 0; s >>= 1) { if (tid < s) red[tid] += red[tid+s]; __syncthreads(); }
    float var = red[0] * (1.f/1152.f) - mu*mu;
    float rstd = rsqrtf(var + 1e-5f);

    int w = 0, s = 0;
    if (v < NS) { w = v / SHOT; s = v % SHOT; }
    #pragma unroll
    for (int ii = 0; ii < 9; ii++) {
        int d = tid + ii*128;
        int h = d / DH, dd = d % DH;
        float o = ((kv[ii] - mu) * rstd * lg[d] + lb[d]) * RS24;  // fold 1/sqrt(24)
        if (v < NS) {
            int zz = w*2 + h;
            g_skz[zz][(size_t)(s*NTUP + t)*DH + dd] = __float2half(o);
            g_svT[zz][(size_t)dd*KPAD + s*NTUP + t] = __float2half(vv[ii]);
        } else {
            g_qk[h][(size_t)((v-NS)*NTUP + t)*DH + dd] = __float2half(o);
            g_qv[(size_t)((v-NS)*NTUP + t)*DIM + d] = vv[ii];
        }
    }
}

// ---------------- softmax: warp per row, f16 in/out ----------------
__global__ __launch_bounds__(256) void k_softmax() {
    const int row = blockIdx.x*8 + (threadIdx.x >> 5);
    const int lane = threadIdx.x & 31;
    const int z = row / KROWS, r = row % KROWS;
    const __half2* src = (const __half2*)(g_scores[z] + (size_t)r * SKP);
    __half2* dst = (__half2*)(g_attn[z] + (size_t)r * KPAD);
    float e0[18], e1[18];
    float mx = -1e30f;
    #pragma unroll
    for (int ii = 0; ii < 18; ii++){
        int i = lane + ii*32;
        if (i < 550) {
            float2 v = __half22float2(src[i]);
            e0[ii] = v.x; e1[ii] = v.y;
            mx = fmaxf(mx, fmaxf(v.x, v.y));
        } else { e0[ii] = -1e30f; e1[ii] = -1e30f; }
    }
    #pragma unroll
    for (int o = 16; o; o >>= 1) mx = fmaxf(mx, __shfl_xor_sync(0xffffffffu, mx, o));
    float sum = 0.f;
    #pragma unroll
    for (int ii = 0; ii < 18; ii++){
        int i = lane + ii*32;
        if (i < 550) {
            e0[ii] = __expf(e0[ii] - mx);
            e1[ii] = __expf(e1[ii] - mx);
            sum += e0[ii] + e1[ii];
        } else { e0[ii] = 0.f; e1[ii] = 0.f; }
    }
    #pragma unroll
    for (int o = 16; o; o >>= 1) sum += __shfl_xor_sync(0xffffffffu, sum, o);
    float inv = 1.f / sum;
    #pragma unroll
    for (int ii = 0; ii < 18; ii++){
        int i = lane + ii*32;
        if (i < 576) dst[i] = __floats2half2_rn(e0[ii]*inv, e1[ii]*inv);
    }
}

// ---------------- launch ----------------
extern "C" void kernel_launch(void* const* d_in, const int* in_sizes, int n_in,
                              void* d_out, int out_size)
{
    const float* support = (const float*)d_in[0];
    const float* queries = (const float*)d_in[1];
    const float* k_w  = (const float*)d_in[3];
    const float* k_b  = (const float*)d_in[4];
    const float* v_w  = (const float*)d_in[5];
    const float* v_b  = (const float*)d_in[6];
    const float* ln_g = (const float*)d_in[7];
    const float* ln_b = (const float*)d_in[8];
    float* out = (float*)d_out;

    void *pAp, *pWT, *pP, *pQK, *pSKZ, *pSVT, *pSC, *pATT, *pQV;
    cudaGetSymbolAddress(&pAp,  g_Ap);
    cudaGetSymbolAddress(&pWT,  g_wT);
    cudaGetSymbolAddress(&pP,   g_P);
    cudaGetSymbolAddress(&pQK,  g_qk);
    cudaGetSymbolAddress(&pSKZ, g_skz);
    cudaGetSymbolAddress(&pSVT, g_svT);
    cudaGetSymbolAddress(&pSC,  g_scores);
    cudaGetSymbolAddress(&pATT, g_attn);
    cudaGetSymbolAddress(&pQV,  g_qv);

    auto gemm_pp = k_gemmh<0,32,64,4,2,3>;   // proj
    auto gemm_sc = k_gemmh<1,32,64,4,2,3>;   // scores
    auto gemm_pr = k_gemmh<2,64,48,2,4,2>;   // proto+logits
    cudaFuncSetAttribute(gemm_pp, cudaFuncAttributeMaxDynamicSharedMemorySize, 3*32768);
    cudaFuncSetAttribute(gemm_sc, cudaFuncAttributeMaxDynamicSharedMemorySize, 3*32768);
    cudaFuncSetAttribute(gemm_pr, cudaFuncAttributeMaxDynamicSharedMemorySize, 2*40960);

    k_init<<<1, 256>>>(out);
    {   // zero svT (K-pad cols) and skz (pad rows) fully
        size_t n1 = (size_t)WAY*HH*DH*KPAD/8;
        k_zero16<<<(int)((n1 + 255)/256), 256>>>((uint4*)pSVT, n1);
        size_t n2 = (size_t)WAY*HH*SKP*DH/8;
        k_zero16<<<(int)((n2 + 255)/256), 256>>>((uint4*)pSKZ, n2);
    }
    k_prepA<<<NV*SEQ, 128>>>(support, queries);
    k_transW<<<dim3(36, 36, 6), dim3(32, 32)>>>(k_w, v_w);

    // proj: C[1024(900), 6912] = Ap @ wT^T, K=1152, fp32 out
    gemm_pp<<<dim3(54, 8, 1), 256, 3*32768>>>(
        (const __half*)pAp, DIM, 1, 0,
        (const __half*)pWT, DIM, 0,
        pP, 6912, 0, 18, nullptr, nullptr);

    k_combine<<<NV*NTUP, 128>>>(k_b, v_b, ln_g, ln_b);

    // scores: per z: C[11008, 1152] = qk[z%2] @ skz[z]^T, K=576, f16 out
    gemm_sc<<<dim3(9, 86, WAY*HH), 256, 3*32768>>>(
        (const __half*)pQK, DH, 2, (size_t)MPAD*DH,
        (const __half*)pSKZ, DH, (size_t)SKP*DH,
        pSC, SKP, (size_t)MPAD*SKP, 9, nullptr, nullptr);

    k_softmax<<<WAY*HH*KROWS/8, 256>>>();

    // proto + fused logits: per z: P[11008,576] = attn[z] @ svT[z]^T, K=1152
    gemm_pr<<<dim3(3, 86, WAY*HH), 256, 2*40960>>>(
        (const __half*)pATT, KPAD, 0, (size_t)MPAD*KPAD,
        (const __half*)pSVT, KPAD, (size_t)DH*KPAD,
        nullptr, 0, 0, 18, (const float*)pQV, out);
}